// round 3
// baseline (speedup 1.0000x reference)
#include <cuda_runtime.h>

// AOLayer: out[b,n,a] = ang * rad, B=512,N=32,A=256,P=6.
// Round 3: issue-slot diet. Pre-packed f32x2 pos pairs in SMEM (LDS.64, no
// pack MOVs), predicated packed angular muls (ISETPs hoisted), dual radial
// accumulators, single-asm packed ex2.

#define A_DIM 256
#define P_DIM 6
#define BN_DIM (512 * 32)
#define ROWS_PER_BLOCK 16
#define NPAIRS (ROWS_PER_BLOCK / 2)

typedef unsigned long long u64;

__device__ __forceinline__ u64 pack2(float lo, float hi) {
    u64 r;
    asm("mov.b64 %0, {%1, %2};" : "=l"(r) : "f"(lo), "f"(hi));
    return r;
}
__device__ __forceinline__ u64 add2(u64 a, u64 b) {
    u64 r; asm("add.rn.f32x2 %0, %1, %2;" : "=l"(r) : "l"(a), "l"(b)); return r;
}
__device__ __forceinline__ u64 mul2(u64 a, u64 b) {
    u64 r; asm("mul.rn.f32x2 %0, %1, %2;" : "=l"(r) : "l"(a), "l"(b)); return r;
}
__device__ __forceinline__ u64 fma2(u64 a, u64 b, u64 c) {
    u64 r; asm("fma.rn.f32x2 %0, %1, %2, %3;" : "=l"(r) : "l"(a), "l"(b), "l"(c)); return r;
}
// packed ex2 on both halves, single asm block (no C-level pack/unpack)
__device__ __forceinline__ u64 ex2_2(u64 x) {
    u64 r;
    asm("{\n\t"
        ".reg .f32 lo, hi;\n\t"
        "mov.b64 {lo, hi}, %1;\n\t"
        "ex2.approx.f32 lo, lo;\n\t"
        "ex2.approx.f32 hi, hi;\n\t"
        "mov.b64 %0, {lo, hi};\n\t"
        "}" : "=l"(r) : "l"(x));
    return r;
}

__global__ void __launch_bounds__(A_DIM) aolayer_kernel(
    const float* __restrict__ pos,      // [BN, 3]
    const float* __restrict__ centers,  // [A, 3]
    const float* __restrict__ exps,     // [A, P]
    const float* __restrict__ coeffs,   // [A, P]
    const int*   __restrict__ powers,   // [A, 3]
    float* __restrict__ out)            // [BN, A]
{
    const int a = threadIdx.x;

    // ---- per-atom constants (once per block) ----
    const float cx = centers[a * 3 + 0];
    const float cy = centers[a * 3 + 1];
    const float cz = centers[a * 3 + 2];
    const u64 ncx2 = pack2(-cx, -cx);
    const u64 ncy2 = pack2(-cy, -cy);
    const u64 ncz2 = pack2(-cz, -cz);

    const float NEG_LOG2E = -1.4426950408889634f;
    u64 ep2[P_DIM], co2[P_DIM];
#pragma unroll
    for (int p = 0; p < P_DIM; p++) {
        float e = exps[a * P_DIM + p] * NEG_LOG2E;
        float c = coeffs[a * P_DIM + p];
        ep2[p] = pack2(e, e);
        co2[p] = pack2(c, c);
    }

    const int px = powers[a * 3 + 0];
    const int py = powers[a * 3 + 1];
    const int pz = powers[a * 3 + 2];
    // loop-invariant predicates -> ptxas hoists ISETPs out of the unrolled loop
    const bool lx = (px >= 1), qx = (px == 2);
    const bool ly = (py >= 1), qy = (py == 2);
    const bool lz = (pz >= 1), qz = (pz == 2);

    // ---- stage pre-packed pos pairs: spos2[pair*3 + dim] = {row 2p, row 2p+1} ----
    __shared__ u64 spos2[NPAIRS * 3];
    const int row0 = blockIdx.x * ROWS_PER_BLOCK;
    if (threadIdx.x < NPAIRS * 3) {
        const int pr = threadIdx.x / 3;
        const int d  = threadIdx.x % 3;
        const float v0 = pos[(row0 + 2 * pr) * 3 + d];
        const float v1 = pos[(row0 + 2 * pr + 1) * 3 + d];
        spos2[threadIdx.x] = pack2(v0, v1);
    }
    __syncthreads();

    float* out_base = out + (size_t)row0 * A_DIM + a;

#pragma unroll
    for (int pr = 0; pr < NPAIRS; pr++) {
        // 3x LDS.64, already packed {row, row+1}
        const u64 dxp = add2(spos2[pr * 3 + 0], ncx2);
        const u64 dyp = add2(spos2[pr * 3 + 1], ncy2);
        const u64 dzp = add2(spos2[pr * 3 + 2], ncz2);

        u64 r2p = mul2(dzp, dzp);
        r2p = fma2(dyp, dyp, r2p);
        r2p = fma2(dxp, dxp, r2p);

        // radial: two independent accumulators
        u64 rad0 = mul2(co2[0], ex2_2(mul2(ep2[0], r2p)));
        u64 rad1 = mul2(co2[1], ex2_2(mul2(ep2[1], r2p)));
        rad0 = fma2(co2[2], ex2_2(mul2(ep2[2], r2p)), rad0);
        rad1 = fma2(co2[3], ex2_2(mul2(ep2[3], r2p)), rad1);
        rad0 = fma2(co2[4], ex2_2(mul2(ep2[4], r2p)), rad0);
        rad1 = fma2(co2[5], ex2_2(mul2(ep2[5], r2p)), rad1);

        u64 o = add2(rad0, rad1);

        // angular as predicated packed muls (predicates loop-invariant)
        if (lx) o = mul2(o, dxp);
        if (qx) o = mul2(o, dxp);
        if (ly) o = mul2(o, dyp);
        if (qy) o = mul2(o, dyp);
        if (lz) o = mul2(o, dzp);
        if (qz) o = mul2(o, dzp);

        float o0, o1;
        asm("mov.b64 {%0, %1}, %2;" : "=f"(o0), "=f"(o1) : "l"(o));
        out_base[(2 * pr) * A_DIM] = o0;
        out_base[(2 * pr + 1) * A_DIM] = o1;
    }
}

extern "C" void kernel_launch(void* const* d_in, const int* in_sizes, int n_in,
                              void* d_out, int out_size) {
    const float* pos     = (const float*)d_in[0];
    const float* centers = (const float*)d_in[1];
    const float* exps    = (const float*)d_in[2];
    const float* coeffs  = (const float*)d_in[3];
    const int*   powers  = (const int*)d_in[4];
    float* out = (float*)d_out;

    dim3 grid(BN_DIM / ROWS_PER_BLOCK);  // 1024 blocks
    dim3 block(A_DIM);                   // 256 threads, one per atom
    aolayer_kernel<<<grid, block>>>(pos, centers, exps, coeffs, powers, out);
}